// round 2
// baseline (speedup 1.0000x reference)
#include <cuda_runtime.h>

static constexpr int D = 128;
static constexpr int K = 8;

// Zero the scalar accumulator (d_out is poisoned to 0xAA before timing and is
// reused across graph replays, so it must be reset every kernel_launch).
__global__ void spl_zero_kernel(float* out) { *out = 0.0f; }

__global__ __launch_bounds__(256) void spl_loss_kernel(
    const float* __restrict__ emb,
    const int*   __restrict__ pair_ids,
    const int*   __restrict__ dims,
    float*       __restrict__ out,
    int n_pairs, float inv_p)
{
    const unsigned FULL = 0xFFFFFFFFu;
    const int lane = threadIdx.x & 31;
    const int wid  = threadIdx.x >> 5;       // 8 warps per block
    const int pair = blockIdx.x * 8 + wid;

    float loss = 0.0f;
    if (pair < n_pairs) {
        // Uniform per-warp load: one transaction, broadcast to all lanes.
        int2 pr = __ldg(((const int2*)pair_ids) + pair);
        const float4* r1 = (const float4*)(emb + (size_t)pr.x * D);
        const float4* r2 = (const float4*)(emb + (size_t)pr.y * D);
        float4 a = __ldg(r1 + lane);   // v1[lane*4 .. lane*4+3]
        float4 b = __ldg(r2 + lane);   // v2[lane*4 .. lane*4+3]

        int mydim = 0;
        if (lane < K) mydim = __ldg(dims + (size_t)pair * K + lane);

        // ---- polarity: lanes 0..7 fetch v1[dim], v2[dim] via shuffle ----
        int src = mydim >> 2;
        int e   = mydim & 3;
        float ax = __shfl_sync(FULL, a.x, src);
        float ay = __shfl_sync(FULL, a.y, src);
        float az = __shfl_sync(FULL, a.z, src);
        float aw = __shfl_sync(FULL, a.w, src);
        float bx = __shfl_sync(FULL, b.x, src);
        float by = __shfl_sync(FULL, b.y, src);
        float bz = __shfl_sync(FULL, b.z, src);
        float bw = __shfl_sync(FULL, b.w, src);
        float a1 = (e == 0) ? ax : (e == 1) ? ay : (e == 2) ? az : aw;
        float a2 = (e == 0) ? bx : (e == 1) ? by : (e == 2) ? bz : bw;

        float pd = 0.0f;
        if (lane < K) {
            float s   = fabsf(a1) + fabsf(a2);
            bool zero = (a1 == 0.0f) || (a2 == 0.0f);            // sign_prod == 0
            bool opp  = ((__float_as_int(a1) ^ __float_as_int(a2)) < 0); // sign bits differ
            pd = zero ? 0.1f : (opp ? -0.5f * s : s);
        }

        // ---- broadcast the 8 dims to all lanes ----
        int dv0 = __shfl_sync(FULL, mydim, 0);
        int dv1 = __shfl_sync(FULL, mydim, 1);
        int dv2 = __shfl_sync(FULL, mydim, 2);
        int dv3 = __shfl_sync(FULL, mydim, 3);
        int dv4 = __shfl_sync(FULL, mydim, 4);
        int dv5 = __shfl_sync(FULL, mydim, 5);
        int dv6 = __shfl_sync(FULL, mydim, 6);
        int dv7 = __shfl_sync(FULL, mydim, 7);

        // ---- similarity: total diff^2 minus contributions of selected dims ----
        float dx = a.x - b.x, dy = a.y - b.y, dz = a.z - b.z, dw = a.w - b.w;
        float t0 = dx * dx, t1 = dy * dy, t2 = dz * dz, t3 = dw * dw;
        int base = lane * 4;

        #define SPL_MEMBER(idx) \
            ((idx) == dv0 || (idx) == dv1 || (idx) == dv2 || (idx) == dv3 || \
             (idx) == dv4 || (idx) == dv5 || (idx) == dv6 || (idx) == dv7)
        bool m0 = SPL_MEMBER(base + 0);
        bool m1 = SPL_MEMBER(base + 1);
        bool m2 = SPL_MEMBER(base + 2);
        bool m3 = SPL_MEMBER(base + 3);
        #undef SPL_MEMBER

        float total   = t0 + t1 + t2 + t3;
        float removed = (m0 ? t0 : 0.0f) + (m1 ? t1 : 0.0f)
                      + (m2 ? t2 : 0.0f) + (m3 ? t3 : 0.0f);
        int   cntrem  = (int)m0 + (int)m1 + (int)m2 + (int)m3;

        // ---- warp reductions ----
        #pragma unroll
        for (int off = 16; off > 0; off >>= 1) {
            pd      += __shfl_xor_sync(FULL, pd,      off);
            total   += __shfl_xor_sync(FULL, total,   off);
            removed += __shfl_xor_sync(FULL, removed, off);
            cntrem  += __shfl_xor_sync(FULL, cntrem,  off);
        }

        int keep  = D - cntrem;                      // distinct-dims complement count
        float sim = (keep > 0) ? (total - removed) / (float)keep : 0.0f;
        loss = pd + 0.5f * sim;                      // POLARITY_WEIGHT=1, SIMILARITY_WEIGHT=0.5
    }

    // ---- block reduce (lane 0 of each warp) + one atomic per block ----
    __shared__ float warp_sums[8];
    if (lane == 0) warp_sums[wid] = loss;
    __syncthreads();
    if (threadIdx.x == 0) {
        float s = 0.0f;
        #pragma unroll
        for (int w = 0; w < 8; w++) s += warp_sums[w];
        atomicAdd(out, s * inv_p);
    }
}

extern "C" void kernel_launch(void* const* d_in, const int* in_sizes, int n_in,
                              void* d_out, int out_size)
{
    const float* emb      = (const float*)d_in[0];  // (VOCAB, 128) f32
    const int*   pair_ids = (const int*)  d_in[1];  // (P, 2) i32
    const int*   dims     = (const int*)  d_in[2];  // (P, 8) i32
    float*       out      = (float*)d_out;          // scalar f32

    int n_pairs = in_sizes[1] / 2;
    spl_zero_kernel<<<1, 1>>>(out);
    int blocks = (n_pairs + 7) / 8;                 // 8 warps (pairs) per 256-thread block
    spl_loss_kernel<<<blocks, 256>>>(emb, pair_ids, dims, out,
                                     n_pairs, 1.0f / (float)n_pairs);
}

// round 3
// speedup vs baseline: 1.0144x; 1.0144x over previous
#include <cuda_runtime.h>

static constexpr int D = 128;
static constexpr int K = 8;

// Zero the scalar accumulator (d_out is poisoned to 0xAA before timing and is
// reused across graph replays, so it must be reset every kernel_launch).
__global__ void spl_zero_kernel(float* out) { *out = 0.0f; }

__global__ __launch_bounds__(256) void spl_loss_kernel(
    const float* __restrict__ emb,
    const int*   __restrict__ pair_ids,
    const int*   __restrict__ dims,
    float*       __restrict__ out,
    int n_pairs, float inv_p)
{
    const unsigned FULL = 0xFFFFFFFFu;
    const int lane = threadIdx.x & 31;
    const int wid  = threadIdx.x >> 5;       // 8 warps per block
    const int pair = blockIdx.x * 8 + wid;

    float loss = 0.0f;
    if (pair < n_pairs) {
        // Uniform per-warp load: one transaction, broadcast to all lanes.
        int2 pr = __ldg(((const int2*)pair_ids) + pair);
        const float4* r1 = (const float4*)(emb + (size_t)pr.x * D);
        const float4* r2 = (const float4*)(emb + (size_t)pr.y * D);
        float4 a = __ldg(r1 + lane);   // v1[lane*4 .. lane*4+3]
        float4 b = __ldg(r2 + lane);   // v2[lane*4 .. lane*4+3]

        int mydim = 0;
        if (lane < K) mydim = __ldg(dims + (size_t)pair * K + lane);

        // ---- polarity: lanes 0..7 fetch v1[dim], v2[dim] via shuffle ----
        int src = mydim >> 2;
        int e   = mydim & 3;
        float ax = __shfl_sync(FULL, a.x, src);
        float ay = __shfl_sync(FULL, a.y, src);
        float az = __shfl_sync(FULL, a.z, src);
        float aw = __shfl_sync(FULL, a.w, src);
        float bx = __shfl_sync(FULL, b.x, src);
        float by = __shfl_sync(FULL, b.y, src);
        float bz = __shfl_sync(FULL, b.z, src);
        float bw = __shfl_sync(FULL, b.w, src);
        float a1 = (e == 0) ? ax : (e == 1) ? ay : (e == 2) ? az : aw;
        float a2 = (e == 0) ? bx : (e == 1) ? by : (e == 2) ? bz : bw;

        float pd = 0.0f;
        if (lane < K) {
            float s   = fabsf(a1) + fabsf(a2);
            bool zero = (a1 == 0.0f) || (a2 == 0.0f);            // sign_prod == 0
            bool opp  = ((__float_as_int(a1) ^ __float_as_int(a2)) < 0); // sign bits differ
            pd = zero ? 0.1f : (opp ? -0.5f * s : s);
        }

        // ---- broadcast the 8 dims to all lanes ----
        int dv0 = __shfl_sync(FULL, mydim, 0);
        int dv1 = __shfl_sync(FULL, mydim, 1);
        int dv2 = __shfl_sync(FULL, mydim, 2);
        int dv3 = __shfl_sync(FULL, mydim, 3);
        int dv4 = __shfl_sync(FULL, mydim, 4);
        int dv5 = __shfl_sync(FULL, mydim, 5);
        int dv6 = __shfl_sync(FULL, mydim, 6);
        int dv7 = __shfl_sync(FULL, mydim, 7);

        // ---- similarity: total diff^2 minus contributions of selected dims ----
        float dx = a.x - b.x, dy = a.y - b.y, dz = a.z - b.z, dw = a.w - b.w;
        float t0 = dx * dx, t1 = dy * dy, t2 = dz * dz, t3 = dw * dw;
        int base = lane * 4;

        #define SPL_MEMBER(idx) \
            ((idx) == dv0 || (idx) == dv1 || (idx) == dv2 || (idx) == dv3 || \
             (idx) == dv4 || (idx) == dv5 || (idx) == dv6 || (idx) == dv7)
        bool m0 = SPL_MEMBER(base + 0);
        bool m1 = SPL_MEMBER(base + 1);
        bool m2 = SPL_MEMBER(base + 2);
        bool m3 = SPL_MEMBER(base + 3);
        #undef SPL_MEMBER

        float total   = t0 + t1 + t2 + t3;
        float removed = (m0 ? t0 : 0.0f) + (m1 ? t1 : 0.0f)
                      + (m2 ? t2 : 0.0f) + (m3 ? t3 : 0.0f);
        int   cntrem  = (int)m0 + (int)m1 + (int)m2 + (int)m3;

        // ---- warp reductions ----
        #pragma unroll
        for (int off = 16; off > 0; off >>= 1) {
            pd      += __shfl_xor_sync(FULL, pd,      off);
            total   += __shfl_xor_sync(FULL, total,   off);
            removed += __shfl_xor_sync(FULL, removed, off);
            cntrem  += __shfl_xor_sync(FULL, cntrem,  off);
        }

        int keep  = D - cntrem;                      // distinct-dims complement count
        float sim = (keep > 0) ? (total - removed) / (float)keep : 0.0f;
        loss = pd + 0.5f * sim;                      // POLARITY_WEIGHT=1, SIMILARITY_WEIGHT=0.5
    }

    // ---- block reduce (lane 0 of each warp) + one atomic per block ----
    __shared__ float warp_sums[8];
    if (lane == 0) warp_sums[wid] = loss;
    __syncthreads();
    if (threadIdx.x == 0) {
        float s = 0.0f;
        #pragma unroll
        for (int w = 0; w < 8; w++) s += warp_sums[w];
        atomicAdd(out, s * inv_p);
    }
}

extern "C" void kernel_launch(void* const* d_in, const int* in_sizes, int n_in,
                              void* d_out, int out_size)
{
    const float* emb      = (const float*)d_in[0];  // (VOCAB, 128) f32
    const int*   pair_ids = (const int*)  d_in[1];  // (P, 2) i32
    const int*   dims     = (const int*)  d_in[2];  // (P, 8) i32
    float*       out      = (float*)d_out;          // scalar f32

    int n_pairs = in_sizes[1] / 2;
    spl_zero_kernel<<<1, 1>>>(out);
    int blocks = (n_pairs + 7) / 8;                 // 8 warps (pairs) per 256-thread block
    spl_loss_kernel<<<blocks, 256>>>(emb, pair_ids, dims, out,
                                     n_pairs, 1.0f / (float)n_pairs);
}